// round 12
// baseline (speedup 1.0000x reference)
#include <cuda_runtime.h>
#include <cuda_bf16.h>
#include <math.h>

#define NUM_LEVELS 16
#define TABLE_SIZE (1u << 19)
#define TSAMP 192
#define PTS 256            // points per block
#define NTHREADS 256
#define FS4 20             // feats row stride in uint4: 20%8==4 -> conflict-free octets
#define WS4 66             // W row stride in uint4:   66%8==2 -> conflict-free octets

struct LevelParams {
    float scale[NUM_LEVELS];
    int   res[NUM_LEVELS];
    unsigned hashed_mask;
};

__device__ __forceinline__ float softplus10(float v) {
    float y = 10.0f * v;
    float t = __expf(-fabsf(y));
    return (fmaxf(y, 0.0f) + __logf(1.0f + t)) * 0.1f;
}

__device__ __forceinline__ unsigned pack_bf16x2(float lo_val, float hi_val) {
    unsigned r;
    asm("cvt.rn.bf16x2.f32 %0, %1, %2;" : "=r"(r) : "f"(hi_val), "f"(lo_val));
    return r;
}

#define MMA_BF16(C, A0, A1, A2, A3, B0, B1)                                    \
    asm volatile(                                                              \
        "mma.sync.aligned.m16n8k16.row.col.f32.bf16.bf16.f32 "                 \
        "{%0,%1,%2,%3}, {%4,%5,%6,%7}, {%8,%9}, {%0,%1,%2,%3};"                \
        : "+f"(C[0]), "+f"(C[1]), "+f"(C[2]), "+f"(C[3])                       \
        : "r"(A0), "r"(A1), "r"(A2), "r"(A3), "r"(B0), "r"(B1));

// gather + bilinear interp for one level -> f0..f3
__device__ __forceinline__ void gather_level(
    int l, float ux, float uy, const LevelParams& lp, const float4* __restrict__ emb,
    float& f0, float& f1, float& f2, float& f3)
{
    float s = lp.scale[l];
    float posx = ux * s + 0.5f;
    float posy = uy * s + 0.5f;
    float pfx = floorf(posx), pfy = floorf(posy);
    float frx = posx - pfx,   fry = posy - pfy;
    int ix = (int)pfx, iy = (int)pfy;

    unsigned i00, i01, i10, i11;
    if ((lp.hashed_mask >> l) & 1u) {
        unsigned hy0 = (unsigned)iy * 2654435761u;
        unsigned hy1 = (unsigned)(iy + 1) * 2654435761u;
        i00 = ((unsigned)ix       ^ hy0) & (TABLE_SIZE - 1u);
        i01 = ((unsigned)ix       ^ hy1) & (TABLE_SIZE - 1u);
        i10 = ((unsigned)(ix + 1) ^ hy0) & (TABLE_SIZE - 1u);
        i11 = ((unsigned)(ix + 1) ^ hy1) & (TABLE_SIZE - 1u);
    } else {
        int res = lp.res[l];
        i00 = (unsigned)(iy * res + ix);
        i01 = i00 + (unsigned)res;
        i10 = i00 + 1u;
        i11 = i01 + 1u;
    }

    const float4* tab = emb + (size_t)l * TABLE_SIZE;
    float4 c00 = __ldg(tab + i00);
    float4 c01 = __ldg(tab + i01);
    float4 c10 = __ldg(tab + i10);
    float4 c11 = __ldg(tab + i11);

    float w00 = (1.0f - frx) * (1.0f - fry);
    float w01 = (1.0f - frx) * fry;
    float w10 = frx * (1.0f - fry);
    float w11 = frx * fry;

    f0 = ((c00.x * w00 + c01.x * w01) + c10.x * w10) + c11.x * w11;
    f1 = ((c00.y * w00 + c01.y * w01) + c10.y * w10) + c11.y * w11;
    f2 = ((c00.z * w00 + c01.z * w01) + c10.z * w10) + c11.z * w11;
    f3 = ((c00.w * w00 + c01.w * w01) + c10.w * w10) + c11.w * w11;
}

__global__ __launch_bounds__(NTHREADS, 2)
void nerf_fused(const float* __restrict__ x,
                const float4* __restrict__ emb,
                const float* __restrict__ W0,
                const float* __restrict__ b0,
                const float* __restrict__ W1,
                const float* __restrict__ b1,
                float* __restrict__ out,
                LevelParams lp)
{
    extern __shared__ unsigned smu[];
    uint4* sF4 = (uint4*)smu;                  // [PTS][FS4]   packed feats
    uint4* sB4 = sF4 + PTS * FS4;              // [16][WS4]    packed W0
    float* sb0 = (float*)(sB4 + 16 * WS4);     // [64]
    float* sW1 = sb0 + 64;                     // [64]
    float* sb1 = sW1 + 64;                     // [1]

    const int tid = threadIdx.x;

    // ---- W0 -> packed uint4 {hi(c),lo(c),hi(c+4),lo(c+4)} per (kk,c,n) ----
    for (int e = tid; e < 1024; e += NTHREADS) {
        int row = e >> 6, n = e & 63;           // row = kk*4 + c
        int kk = row >> 2, cc = row & 3;
        int k2a = kk * 8 + cc;
        int k2b = k2a + 4;
        float wa0 = W0[(2 * k2a) * 64 + n];
        float wa1 = W0[(2 * k2a + 1) * 64 + n];
        float wb0 = W0[(2 * k2b) * 64 + n];
        float wb1 = W0[(2 * k2b + 1) * 64 + n];
        float ha0 = __bfloat162float(__float2bfloat16(wa0));
        float ha1 = __bfloat162float(__float2bfloat16(wa1));
        float hb0 = __bfloat162float(__float2bfloat16(wb0));
        float hb1 = __bfloat162float(__float2bfloat16(wb1));
        uint4 v;
        v.x = pack_bf16x2(ha0, ha1);
        v.y = pack_bf16x2(wa0 - ha0, wa1 - ha1);
        v.z = pack_bf16x2(hb0, hb1);
        v.w = pack_bf16x2(wb0 - hb0, wb1 - hb1);
        sB4[row * WS4 + n] = v;
    }
    if (tid < 64) { sb0[tid] = b0[tid]; sW1[tid] = W1[tid]; }
    if (tid == 0) { sb1[0] = b1[0]; }

    // ---- Phase 1: gather; 1 thread per point, all 16 levels ----
    const int pt  = tid;
    const int p   = blockIdx.x * PTS + pt;
    const int ray = p / TSAMP;
    const int t   = p - ray * TSAMP;

    const float2* xr = (const float2*)(x + (size_t)ray * (TSAMP * 2));
    float2 o  = xr[0];
    float2 en = xr[TSAMP - 1];
    float dxr = en.x - o.x, dyr = en.y - o.y;
    float nrm = sqrtf(dxr * dxr + dyr * dyr);
    dxr /= nrm; dyr /= nrm;

    const float step = 2.0f / 191.0f;
    float z  = step * (float)t;
    float ux = (fminf(fmaxf(o.x + dxr * z, -1.0f), 1.0f) + 1.0f) * 0.5f;
    float uy = (fminf(fmaxf(o.y + dyr * z, -1.0f), 1.0f) + 1.0f) * 0.5f;

    uint4* f_row = sF4 + pt * FS4;
    #pragma unroll
    for (int j = 0; j < 4; ++j) {
        #pragma unroll
        for (int b = 0; b < 2; ++b) {
            int la = 4 * j + b;                 // fills .xy
            int lb = la + 2;                    // fills .zw
            float fa0, fa1, fa2, fa3, fb0, fb1, fb2, fb3;
            gather_level(la, ux, uy, lp, emb, fa0, fa1, fa2, fa3);
            gather_level(lb, ux, uy, lp, emb, fb0, fb1, fb2, fb3);

            float ha0 = __bfloat162float(__float2bfloat16(fa0));
            float ha1 = __bfloat162float(__float2bfloat16(fa1));
            float ha2 = __bfloat162float(__float2bfloat16(fa2));
            float ha3 = __bfloat162float(__float2bfloat16(fa3));
            float hb0 = __bfloat162float(__float2bfloat16(fb0));
            float hb1 = __bfloat162float(__float2bfloat16(fb1));
            float hb2 = __bfloat162float(__float2bfloat16(fb2));
            float hb3 = __bfloat162float(__float2bfloat16(fb3));

            uint4 v0, v1;
            v0.x = pack_bf16x2(ha0, ha1);
            v0.y = pack_bf16x2(fa0 - ha0, fa1 - ha1);
            v0.z = pack_bf16x2(hb0, hb1);
            v0.w = pack_bf16x2(fb0 - hb0, fb1 - hb1);
            v1.x = pack_bf16x2(ha2, ha3);
            v1.y = pack_bf16x2(fa2 - ha2, fa3 - ha3);
            v1.z = pack_bf16x2(hb2, hb3);
            v1.w = pack_bf16x2(fb2 - hb2, fb3 - hb3);

            int e0 = j * 4 + 2 * b;
            f_row[e0]     = v0;
            f_row[e0 + 1] = v1;
        }
    }

    __syncthreads();

    // ---- Phase 2: per-warp 32x64 tile = two m16n8k16 row tiles sharing B ----
    const int warp = tid >> 5;
    const int lane = tid & 31;
    const int r = lane >> 2;
    const int c = lane & 3;

    const uint4* Ab0 = sF4 + (warp * 32) * FS4;        // rows warp*32 .. +16
    const uint4* Ab1 = Ab0 + 16 * FS4;                 // rows warp*32+16 .. +32
    float sigA0 = 0.f, sigA1 = 0.f;                    // tile 0
    float sigB0 = 0.f, sigB1 = 0.f;                    // tile 1

    #pragma unroll
    for (int ch = 0; ch < 2; ++ch) {
        float C0[4][4], C1[4][4];
        #pragma unroll
        for (int nt = 0; nt < 4; ++nt) {               // fold b0 into accum init
            int col0 = ch * 32 + nt * 8 + 2 * c;
            float ba = sb0[col0], bb = sb0[col0 + 1];
            C0[nt][0] = ba; C0[nt][1] = bb; C0[nt][2] = ba; C0[nt][3] = bb;
            C1[nt][0] = ba; C1[nt][1] = bb; C1[nt][2] = ba; C1[nt][3] = bb;
        }

        #pragma unroll
        for (int kk = 0; kk < 4; ++kk) {
            int e = kk * 4 + c;
            uint4 A0 = Ab0[r * FS4 + e];               // {a0hi,a0lo,a2hi,a2lo}
            uint4 A1 = Ab0[(r + 8) * FS4 + e];
            uint4 A2 = Ab1[r * FS4 + e];
            uint4 A3 = Ab1[(r + 8) * FS4 + e];

            const uint4* Brow = sB4 + e * WS4 + ch * 32;
            #pragma unroll
            for (int nt = 0; nt < 4; ++nt) {
                uint4 B = Brow[nt * 8 + r];            // shared by both tiles
                MMA_BF16(C0[nt], A0.x, A1.x, A0.z, A1.z, B.x, B.z);
                MMA_BF16(C0[nt], A0.x, A1.x, A0.z, A1.z, B.y, B.w);
                MMA_BF16(C0[nt], A0.y, A1.y, A0.w, A1.w, B.x, B.z);
                MMA_BF16(C1[nt], A2.x, A3.x, A2.z, A3.z, B.x, B.z);
                MMA_BF16(C1[nt], A2.x, A3.x, A2.z, A3.z, B.y, B.w);
                MMA_BF16(C1[nt], A2.y, A3.y, A2.w, A3.w, B.x, B.z);
            }
        }

        // partial epilogue for this column half
        #pragma unroll
        for (int nt = 0; nt < 4; ++nt) {
            int col0 = ch * 32 + nt * 8 + 2 * c;
            float w1a = sW1[col0], w1b = sW1[col0 + 1];
            sigA0 += softplus10(C0[nt][0]) * w1a;
            sigA0 += softplus10(C0[nt][1]) * w1b;
            sigA1 += softplus10(C0[nt][2]) * w1a;
            sigA1 += softplus10(C0[nt][3]) * w1b;
            sigB0 += softplus10(C1[nt][0]) * w1a;
            sigB0 += softplus10(C1[nt][1]) * w1b;
            sigB1 += softplus10(C1[nt][2]) * w1a;
            sigB1 += softplus10(C1[nt][3]) * w1b;
        }
    }

    sigA0 += __shfl_xor_sync(0xffffffffu, sigA0, 1);
    sigA0 += __shfl_xor_sync(0xffffffffu, sigA0, 2);
    sigA1 += __shfl_xor_sync(0xffffffffu, sigA1, 1);
    sigA1 += __shfl_xor_sync(0xffffffffu, sigA1, 2);
    sigB0 += __shfl_xor_sync(0xffffffffu, sigB0, 1);
    sigB0 += __shfl_xor_sync(0xffffffffu, sigB0, 2);
    sigB1 += __shfl_xor_sync(0xffffffffu, sigB1, 1);
    sigB1 += __shfl_xor_sync(0xffffffffu, sigB1, 2);

    if (c == 0) {
        float b1v = sb1[0];
        #pragma unroll
        for (int tile = 0; tile < 2; ++tile) {
            #pragma unroll
            for (int hrow = 0; hrow < 2; ++hrow) {
                int local = warp * 32 + tile * 16 + hrow * 8 + r;
                int pp = blockIdx.x * PTS + local;
                int rr = pp / TSAMP;
                int tt = pp - rr * TSAMP;
                float sigv = (tile == 0) ? ((hrow == 0) ? sigA0 : sigA1)
                                         : ((hrow == 0) ? sigB0 : sigB1);
                float sigma = softplus10(b1v + sigv);
                float zt  = step * (float)tt;
                float zt1 = step * (float)(tt - 1);
                float delta = (tt == 0) ? (1.0f / 192.0f) : (zt - zt1);
                out[pp] = delta * sigma;
            }
        }
    }
}

extern "C" void kernel_launch(void* const* d_in, const int* in_sizes, int n_in,
                              void* d_out, int out_size) {
    const float* x   = (const float*)d_in[0];   // [4,2048,192,2]
    const float* emb = (const float*)d_in[1];   // [16, 524288, 4]
    const float* W0  = (const float*)d_in[2];   // [64,64]
    const float* b0  = (const float*)d_in[3];   // [64]
    const float* W1  = (const float*)d_in[4];   // [64,1]
    const float* b1  = (const float*)d_in[5];   // [1]
    float* out = (float*)d_out;

    LevelParams lp;
    const double b = exp((log(2048.0) - log(2.0)) / 15.0);
    unsigned mask = 0;
    for (int l = 0; l < NUM_LEVELS; ++l) {
        double s = 2.0 * pow(b, (double)l) - 1.0;
        lp.scale[l] = (float)s;
        int res = (int)ceil(s) + 1;
        lp.res[l] = res;
        if ((long long)res * (long long)res > (long long)TABLE_SIZE)
            mask |= (1u << l);
    }
    lp.hashed_mask = mask;

    const int smem_bytes = (PTS * FS4 + 16 * WS4) * 16 + (64 + 64 + 4) * 4;
    static int attr_set = 0;
    if (!attr_set) {
        cudaFuncSetAttribute(nerf_fused,
                             cudaFuncAttributeMaxDynamicSharedMemorySize,
                             smem_bytes);
        attr_set = 1;
    }

    int n_points = in_sizes[0] / 2;             // 1,572,864
    int n_blocks = n_points / PTS;              // 6144
    nerf_fused<<<n_blocks, NTHREADS, smem_bytes>>>(x, (const float4*)emb,
                                                   W0, b0, W1, b1, out, lp);
}

// round 13
// speedup vs baseline: 1.1706x; 1.1706x over previous
#include <cuda_runtime.h>
#include <cuda_bf16.h>
#include <math.h>

#define NUM_LEVELS 16
#define TABLE_SIZE (1u << 19)
#define TSAMP 192
#define PTS 128            // points per block
#define NTHREADS 256
#define FS64 36            // feats row stride, uint2(8B) units: (4r+c)%16 bijective
#define WS64 68            // W row stride, uint2 units: (4c+r)%16 bijective

struct LevelParams {
    float scale[NUM_LEVELS];
    int   res[NUM_LEVELS];
    unsigned hashed_mask;
};

__device__ __forceinline__ float softplus10(float v) {
    float y = 10.0f * v;
    float t = __expf(-fabsf(y));
    return (fmaxf(y, 0.0f) + __logf(1.0f + t)) * 0.1f;
}

__device__ __forceinline__ unsigned pack_bf16x2(float lo_val, float hi_val) {
    unsigned r;
    asm("cvt.rn.bf16x2.f32 %0, %1, %2;" : "=r"(r) : "f"(hi_val), "f"(lo_val));
    return r;
}

#define MMA_BF16(C, A0, A1, A2, A3, B0, B1)                                    \
    asm volatile(                                                              \
        "mma.sync.aligned.m16n8k16.row.col.f32.bf16.bf16.f32 "                 \
        "{%0,%1,%2,%3}, {%4,%5,%6,%7}, {%8,%9}, {%0,%1,%2,%3};"                \
        : "+f"(C[0]), "+f"(C[1]), "+f"(C[2]), "+f"(C[3])                       \
        : "r"(A0), "r"(A1), "r"(A2), "r"(A3), "r"(B0), "r"(B1));

// corner indices + fractional coords for one level
__device__ __forceinline__ void level_idx(
    int l, float ux, float uy, const LevelParams& lp,
    unsigned& i00, unsigned& i01, unsigned& i10, unsigned& i11,
    float& frx, float& fry)
{
    float s = lp.scale[l];
    float posx = ux * s + 0.5f;
    float posy = uy * s + 0.5f;
    float pfx = floorf(posx), pfy = floorf(posy);
    frx = posx - pfx; fry = posy - pfy;
    int ix = (int)pfx, iy = (int)pfy;

    if ((lp.hashed_mask >> l) & 1u) {
        unsigned hy0 = (unsigned)iy * 2654435761u;
        unsigned hy1 = (unsigned)(iy + 1) * 2654435761u;
        i00 = ((unsigned)ix       ^ hy0) & (TABLE_SIZE - 1u);
        i01 = ((unsigned)ix       ^ hy1) & (TABLE_SIZE - 1u);
        i10 = ((unsigned)(ix + 1) ^ hy0) & (TABLE_SIZE - 1u);
        i11 = ((unsigned)(ix + 1) ^ hy1) & (TABLE_SIZE - 1u);
    } else {
        int res = lp.res[l];
        i00 = (unsigned)(iy * res + ix);
        i01 = i00 + (unsigned)res;
        i10 = i00 + 1u;
        i11 = i01 + 1u;
    }
}

// bilinear interp + bf16 hi/lo split + 16B store into feats row
__device__ __forceinline__ void interp_store(
    int l, float4 c00, float4 c01, float4 c10, float4 c11,
    float frx, float fry, uint2* f_row)
{
    float w00 = (1.0f - frx) * (1.0f - fry);
    float w01 = (1.0f - frx) * fry;
    float w10 = frx * (1.0f - fry);
    float w11 = frx * fry;

    float f0 = ((c00.x * w00 + c01.x * w01) + c10.x * w10) + c11.x * w11;
    float f1 = ((c00.y * w00 + c01.y * w01) + c10.y * w10) + c11.y * w11;
    float f2 = ((c00.z * w00 + c01.z * w01) + c10.z * w10) + c11.z * w11;
    float f3 = ((c00.w * w00 + c01.w * w01) + c10.w * w10) + c11.w * w11;

    float h0 = __bfloat162float(__float2bfloat16(f0));
    float h1 = __bfloat162float(__float2bfloat16(f1));
    float h2 = __bfloat162float(__float2bfloat16(f2));
    float h3 = __bfloat162float(__float2bfloat16(f3));

    uint4 pk;
    pk.x = pack_bf16x2(h0, h1);
    pk.y = pack_bf16x2(f0 - h0, f1 - h1);
    pk.z = pack_bf16x2(h2, h3);
    pk.w = pack_bf16x2(f2 - h2, f3 - h3);
    *(uint4*)(f_row + l * 2) = pk;
}

// full gather+interp+store for a (direct) level
__device__ __forceinline__ void gather_store(
    int l, float ux, float uy, const LevelParams& lp,
    const float4* __restrict__ emb, uint2* f_row)
{
    unsigned i00, i01, i10, i11; float frx, fry;
    level_idx(l, ux, uy, lp, i00, i01, i10, i11, frx, fry);
    const float4* tab = emb + (size_t)l * TABLE_SIZE;
    float4 c00 = __ldg(tab + i00);
    float4 c01 = __ldg(tab + i01);
    float4 c10 = __ldg(tab + i10);
    float4 c11 = __ldg(tab + i11);
    interp_store(l, c00, c01, c10, c11, frx, fry, f_row);
}

__global__ __launch_bounds__(NTHREADS, 3)
void nerf_fused(const float* __restrict__ x,
                const float4* __restrict__ emb,
                const float* __restrict__ W0,
                const float* __restrict__ b0,
                const float* __restrict__ W1,
                const float* __restrict__ b1,
                float* __restrict__ out,
                LevelParams lp)
{
    extern __shared__ unsigned smu[];
    uint2* FHL = (uint2*)smu;                  // [PTS][FS64]  {hi,lo} bf16x2 feats
    uint2* BHL = FHL + PTS * FS64;             // [32][WS64]   {hi,lo} bf16x2 W0
    float* sb0 = (float*)(BHL + 32 * WS64);    // [64]
    float* sW1 = sb0 + 64;                     // [64]
    float* sb1 = sW1 + 64;                     // [1]

    const int tid = threadIdx.x;

    // ---- W0 -> bf16 {hi,lo}, packed over k-pairs, interleaved ----
    for (int e = tid; e < 2048; e += NTHREADS) {
        int k2 = e >> 6, n = e & 63;
        float w0v = W0[(2 * k2) * 64 + n];
        float w1v = W0[(2 * k2 + 1) * 64 + n];
        float h0f = __bfloat162float(__float2bfloat16(w0v));
        float h1f = __bfloat162float(__float2bfloat16(w1v));
        uint2 v;
        v.x = pack_bf16x2(h0f, h1f);
        v.y = pack_bf16x2(w0v - h0f, w1v - h1f);
        BHL[k2 * WS64 + n] = v;
    }
    if (tid < 64) { sb0[tid] = b0[tid]; sW1[tid] = W1[tid]; }
    if (tid == 0) { sb1[0] = b1[0]; }

    // ---- Phase 1: gather; 2 threads/point, interleaved levels;
    //      hashed-level loads issued FIRST, consumed LAST (latency overlap) ----
    const int pt   = tid & (PTS - 1);
    const int half = tid >> 7;                  // warp-uniform: warps 0-3 / 4-7
    const int p    = blockIdx.x * PTS + pt;
    const int ray  = p / TSAMP;
    const int t    = p - ray * TSAMP;

    const float2* xr = (const float2*)(x + (size_t)ray * (TSAMP * 2));
    float2 o  = xr[0];
    float2 en = xr[TSAMP - 1];
    float dxr = en.x - o.x, dyr = en.y - o.y;
    float nrm = sqrtf(dxr * dxr + dyr * dyr);
    dxr /= nrm; dyr /= nrm;

    const float step = 2.0f / 191.0f;
    float z  = step * (float)t;
    float ux = (fminf(fmaxf(o.x + dxr * z, -1.0f), 1.0f) + 1.0f) * 0.5f;
    float uy = (fminf(fmaxf(o.y + dyr * z, -1.0f), 1.0f) + 1.0f) * 0.5f;

    uint2* f_row = FHL + pt * FS64;

    if (half == 0) {
        // even levels: hashed {14}, direct {0,2,4,6,8,10,12}
        unsigned a0, a1, a2, a3; float afx, afy;
        level_idx(14, ux, uy, lp, a0, a1, a2, a3, afx, afy);
        const float4* tabA = emb + (size_t)14 * TABLE_SIZE;
        float4 A00 = __ldg(tabA + a0);
        float4 A01 = __ldg(tabA + a1);
        float4 A10 = __ldg(tabA + a2);
        float4 A11 = __ldg(tabA + a3);

        #pragma unroll
        for (int i = 0; i < 7; ++i)
            gather_store(2 * i, ux, uy, lp, emb, f_row);

        interp_store(14, A00, A01, A10, A11, afx, afy, f_row);
    } else {
        // odd levels: hashed {13,15}, direct {1,3,5,7,9,11}
        unsigned a0, a1, a2, a3; float afx, afy;
        level_idx(13, ux, uy, lp, a0, a1, a2, a3, afx, afy);
        const float4* tabA = emb + (size_t)13 * TABLE_SIZE;
        float4 A00 = __ldg(tabA + a0);
        float4 A01 = __ldg(tabA + a1);
        float4 A10 = __ldg(tabA + a2);
        float4 A11 = __ldg(tabA + a3);

        unsigned b0i, b1i, b2i, b3i; float bfx, bfy;
        level_idx(15, ux, uy, lp, b0i, b1i, b2i, b3i, bfx, bfy);
        const float4* tabB = emb + (size_t)15 * TABLE_SIZE;
        float4 B00 = __ldg(tabB + b0i);
        float4 B01 = __ldg(tabB + b1i);
        float4 B10 = __ldg(tabB + b2i);
        float4 B11 = __ldg(tabB + b3i);

        #pragma unroll
        for (int i = 0; i < 6; ++i)
            gather_store(2 * i + 1, ux, uy, lp, emb, f_row);

        interp_store(13, A00, A01, A10, A11, afx, afy, f_row);
        interp_store(15, B00, B01, B10, B11, bfx, bfy, f_row);
    }

    __syncthreads();

    // ---- Phase 2: per-warp m16n8k16 bf16 GEMM, 3-pass split, LDS.64 ----
    // Two sequential 32-column halves: C stays 4x4 -> low reg pressure.
    const int warp = tid >> 5;
    const int lane = tid & 31;
    const int r = lane >> 2;
    const int c = lane & 3;

    const uint2* Ab = FHL + (warp * 16) * FS64;
    float sig0 = 0.f, sig1 = 0.f;

    #pragma unroll
    for (int ch = 0; ch < 2; ++ch) {
        float C[4][4];
        #pragma unroll
        for (int nt = 0; nt < 4; ++nt) {        // fold b0 into accumulator init
            int col0 = ch * 32 + nt * 8 + 2 * c;
            float ba = sb0[col0], bb = sb0[col0 + 1];
            C[nt][0] = ba; C[nt][1] = bb; C[nt][2] = ba; C[nt][3] = bb;
        }

        #pragma unroll
        for (int kk = 0; kk < 4; ++kk) {
            int kb2 = kk * 8;
            uint2 a0 = Ab[r * FS64 + kb2 + c];         // .x = hi, .y = lo
            uint2 a1 = Ab[(r + 8) * FS64 + kb2 + c];
            uint2 a2 = Ab[r * FS64 + kb2 + c + 4];
            uint2 a3 = Ab[(r + 8) * FS64 + kb2 + c + 4];

            const uint2* B0 = BHL + (kb2 + c) * WS64 + ch * 32;
            const uint2* B4 = BHL + (kb2 + c + 4) * WS64 + ch * 32;
            #pragma unroll
            for (int nt = 0; nt < 4; ++nt) {
                int n = nt * 8 + r;
                uint2 bv0 = B0[n];
                uint2 bv1 = B4[n];
                MMA_BF16(C[nt], a0.x, a1.x, a2.x, a3.x, bv0.x, bv1.x);
                MMA_BF16(C[nt], a0.x, a1.x, a2.x, a3.x, bv0.y, bv1.y);
                MMA_BF16(C[nt], a0.y, a1.y, a2.y, a3.y, bv0.x, bv1.x);
            }
        }

        // partial epilogue for this column half
        #pragma unroll
        for (int nt = 0; nt < 4; ++nt) {
            int col0 = ch * 32 + nt * 8 + 2 * c;
            float w1a = sW1[col0], w1b = sW1[col0 + 1];
            sig0 += softplus10(C[nt][0]) * w1a;
            sig0 += softplus10(C[nt][1]) * w1b;
            sig1 += softplus10(C[nt][2]) * w1a;
            sig1 += softplus10(C[nt][3]) * w1b;
        }
    }

    sig0 += __shfl_xor_sync(0xffffffffu, sig0, 1);
    sig0 += __shfl_xor_sync(0xffffffffu, sig0, 2);
    sig1 += __shfl_xor_sync(0xffffffffu, sig1, 1);
    sig1 += __shfl_xor_sync(0xffffffffu, sig1, 2);

    if (c == 0) {
        float b1v = sb1[0];
        #pragma unroll
        for (int hrow = 0; hrow < 2; ++hrow) {
            int local = warp * 16 + r + hrow * 8;
            int pp = blockIdx.x * PTS + local;
            int rr = pp / TSAMP;
            int tt = pp - rr * TSAMP;
            float sigv  = (hrow == 0) ? sig0 : sig1;
            float sigma = softplus10(b1v + sigv);
            float zt  = step * (float)tt;
            float zt1 = step * (float)(tt - 1);
            float delta = (tt == 0) ? (1.0f / 192.0f) : (zt - zt1);
            out[pp] = delta * sigma;
        }
    }
}

extern "C" void kernel_launch(void* const* d_in, const int* in_sizes, int n_in,
                              void* d_out, int out_size) {
    const float* x   = (const float*)d_in[0];   // [4,2048,192,2]
    const float* emb = (const float*)d_in[1];   // [16, 524288, 4]
    const float* W0  = (const float*)d_in[2];   // [64,64]
    const float* b0  = (const float*)d_in[3];   // [64]
    const float* W1  = (const float*)d_in[4];   // [64,1]
    const float* b1  = (const float*)d_in[5];   // [1]
    float* out = (float*)d_out;

    LevelParams lp;
    const double b = exp((log(2048.0) - log(2.0)) / 15.0);
    unsigned mask = 0;
    for (int l = 0; l < NUM_LEVELS; ++l) {
        double s = 2.0 * pow(b, (double)l) - 1.0;
        lp.scale[l] = (float)s;
        int res = (int)ceil(s) + 1;
        lp.res[l] = res;
        if ((long long)res * (long long)res > (long long)TABLE_SIZE)
            mask |= (1u << l);
    }
    lp.hashed_mask = mask;

    const int smem_bytes = (PTS * FS64 + 32 * WS64) * 8 + (64 + 64 + 4) * 4;
    static int attr_set = 0;
    if (!attr_set) {
        cudaFuncSetAttribute(nerf_fused,
                             cudaFuncAttributeMaxDynamicSharedMemorySize,
                             smem_bytes);
        attr_set = 1;
    }

    int n_points = in_sizes[0] / 2;             // 1,572,864
    int n_blocks = n_points / PTS;              // 12288
    nerf_fused<<<n_blocks, NTHREADS, smem_bytes>>>(x, (const float4*)emb,
                                                   W0, b0, W1, b1, out, lp);
}